// round 1
// baseline (speedup 1.0000x reference)
#include <cuda_runtime.h>
#include <math.h>

#define NBLK 128
#define NTHR 256
#define WPC  8                 // warps per CTA
#define TOTW (NBLK*WPC)        // 1024 warps
#define HID  128
#define BINS 513
#define WIN  1024
#define ENCN 256

// ---------------- device scratch (no allocations allowed) ----------------
__device__ float g_h1[HID], g_h2[HID], g_h1b[HID], g_h2b[HID];
__device__ float g_specr[BINS], g_speci[BINS];
__device__ float g_y1[WIN];
__device__ float g_enc[ENCN];
__device__ float g_est[ENCN];
__device__ float g_twc[WIN], g_tws[WIN];
__device__ unsigned g_barcnt;   // zero-initialized; self-resetting
__device__ unsigned g_bargen;   // monotonically increasing generation

__device__ __forceinline__ float wsum(float v){
#pragma unroll
    for (int o = 16; o > 0; o >>= 1) v += __shfl_xor_sync(0xffffffffu, v, o);
    return v;
}

__device__ __forceinline__ float sigm(float x){ return 1.0f/(1.0f+__expf(-x)); }

// Grid-wide barrier. Safe because grid (128 CTAs, 256thr, ~9KB smem, occ>=1)
// is entirely resident in wave 1 on a 148-SM GB300.
__device__ __forceinline__ void gsync(){
    __threadfence();            // release: make this thread's writes visible
    __syncthreads();
    if (threadIdx.x == 0){
        unsigned gen = *((volatile unsigned*)&g_bargen);
        unsigned arr = atomicAdd(&g_barcnt, 1u);
        if (arr == NBLK-1){
            g_barcnt = 0;
            __threadfence();
            atomicAdd(&g_bargen, 1u);
        } else {
            while (*((volatile unsigned*)&g_bargen) == gen) { __nanosleep(40); }
        }
    }
    __syncthreads();
    __threadfence();            // acquire: order subsequent loads
}

// One warp computes one LSTM hidden unit j: all four gate dot products fused.
__device__ __forceinline__ void lstm_unit(
    int j, int lane,
    const float* x, int nx,                       // input vector (global or shared)
    const float* __restrict__ hvec,               // previous hidden state
    const float* __restrict__ wih, const float* __restrict__ whh,
    const float* __restrict__ bih, const float* __restrict__ bhh,
    float cprev,
    float* hscr, float* hout, float* cout)        // scratch h, out h, out c
{
    float ai=0.f, af=0.f, ag=0.f, ao=0.f;
    const float* wi0 = wih + (size_t)(0*HID+j)*nx;
    const float* wi1 = wih + (size_t)(1*HID+j)*nx;
    const float* wi2 = wih + (size_t)(2*HID+j)*nx;
    const float* wi3 = wih + (size_t)(3*HID+j)*nx;
    for (int k = lane; k < nx; k += 32){
        float xv = x[k];
        ai = fmaf(wi0[k], xv, ai);
        af = fmaf(wi1[k], xv, af);
        ag = fmaf(wi2[k], xv, ag);
        ao = fmaf(wi3[k], xv, ao);
    }
    const float* wh0 = whh + (0*HID+j)*HID;
    const float* wh1 = whh + (1*HID+j)*HID;
    const float* wh2 = whh + (2*HID+j)*HID;
    const float* wh3 = whh + (3*HID+j)*HID;
#pragma unroll
    for (int k = lane; k < HID; k += 32){
        float hv = hvec[k];
        ai = fmaf(wh0[k], hv, ai);
        af = fmaf(wh1[k], hv, af);
        ag = fmaf(wh2[k], hv, ag);
        ao = fmaf(wh3[k], hv, ao);
    }
    ai = wsum(ai); af = wsum(af); ag = wsum(ag); ao = wsum(ao);
    if (lane == 0){
        ai += bih[j]        + bhh[j];
        af += bih[HID+j]    + bhh[HID+j];
        ag += bih[2*HID+j]  + bhh[2*HID+j];
        ao += bih[3*HID+j]  + bhh[3*HID+j];
        float c2 = sigm(af)*cprev + sigm(ai)*tanhf(ag);
        float h2 = sigm(ao)*tanhf(c2);
        *hscr = h2; *hout = h2; *cout = c2;
    }
}

__global__ void __launch_bounds__(NTHR, 1) dtln_kernel(
    const float* __restrict__ mag,   const float* __restrict__ phase,
    const float* __restrict__ st1,   const float* __restrict__ st2,
    const float* __restrict__ wih10, const float* __restrict__ whh10,
    const float* __restrict__ bih10, const float* __restrict__ bhh10,
    const float* __restrict__ wih11, const float* __restrict__ whh11,
    const float* __restrict__ bih11, const float* __restrict__ bhh11,
    const float* __restrict__ d1w,   const float* __restrict__ d1b,
    const float* __restrict__ encw,  const float* __restrict__ gamma_,
    const float* __restrict__ beta_,
    const float* __restrict__ wih20, const float* __restrict__ whh20,
    const float* __restrict__ bih20, const float* __restrict__ bhh20,
    const float* __restrict__ wih21, const float* __restrict__ whh21,
    const float* __restrict__ bih21, const float* __restrict__ bhh21,
    const float* __restrict__ d2w,   const float* __restrict__ d2b,
    const float* __restrict__ decw,
    float* __restrict__ out)
{
    const int tid  = threadIdx.x;
    const int lane = tid & 31;
    const int wid  = tid >> 5;
    const int gw   = blockIdx.x * WPC + wid;      // global warp id 0..1023

    __shared__ float s_twc[WIN];
    __shared__ float s_tws[WIN];
    __shared__ float s_encn[ENCN];
    __shared__ float s_ra[WPC];
    __shared__ float s_rb[WPC];

    // ---- Stage 1: twiddle table (independent) + LSTM1 layer0 ----
    {
        int gt = blockIdx.x * NTHR + tid;
        if (gt < WIN){
            float s, c;
            sincospif((float)gt * (1.0f/512.0f), &s, &c);   // angle = 2*pi*gt/1024
            g_twc[gt] = c; g_tws[gt] = s;
        }
    }
    if (gw < HID){
        int j = gw;
        lstm_unit(j, lane, mag, BINS, st1 /*h layer0*/,
                  wih10, whh10, bih10, bhh10, st1[2*HID + j],
                  &g_h1[j], &out[WIN + j], &out[WIN + 2*HID + j]);
    }
    gsync();

    // ---- Stage 2: LSTM1 layer1 ----
    if (gw < HID){
        int j = gw;
        lstm_unit(j, lane, g_h1, HID, st1 + HID /*h layer1*/,
                  wih11, whh11, bih11, bhh11, st1[3*HID + j],
                  &g_h2[j], &out[WIN + HID + j], &out[WIN + 3*HID + j]);
    }
    gsync();

    // ---- Stage 3: dense1 mask -> complex spectrum ----
    for (int r = gw; r < BINS; r += TOTW){
        const float* wr = d1w + (size_t)r*HID;
        float acc = 0.f;
#pragma unroll
        for (int k = lane; k < HID; k += 32) acc = fmaf(wr[k], g_h2[k], acc);
        acc = wsum(acc);
        if (lane == 0){
            float m  = sigm(acc + d1b[r]);
            float em = m * mag[r];
            float sp, cp;
            sincosf(phase[r], &sp, &cp);
            g_specr[r] = em * cp;
            g_speci[r] = em * sp;
        }
    }
    gsync();

    // ---- Stage 4: irfft via real DFT with twiddle table ----
    for (int m = tid; m < WIN; m += NTHR){ s_twc[m] = g_twc[m]; s_tws[m] = g_tws[m]; }
    __syncthreads();
    for (int n = gw; n < WIN; n += TOTW){
        float acc = 0.f;
        for (int k = 1 + lane; k < 512; k += 32){
            int idx = (k * n) & (WIN-1);
            acc += g_specr[k]*s_twc[idx] - g_speci[k]*s_tws[idx];
        }
        acc = wsum(acc);
        if (lane == 0){
            float nyq = (n & 1) ? -g_specr[512] : g_specr[512];
            g_y1[n] = (g_specr[0] + 2.0f*acc + nyq) * (1.0f/1024.0f);
        }
    }
    gsync();

    // ---- Stage 5: encoder matvec (256 x 1024) ----
    for (int e = gw; e < ENCN; e += TOTW){
        const float* wr = encw + (size_t)e*WIN;
        float acc = 0.f;
#pragma unroll 4
        for (int k = lane; k < WIN; k += 32) acc = fmaf(wr[k], g_y1[k], acc);
        acc = wsum(acc);
        if (lane == 0) g_enc[e] = acc;
    }
    gsync();

    // ---- Stage 6: instance-norm (per-CTA, shared) + LSTM2 layer0 ----
    if (blockIdx.x < (HID + WPC - 1)/WPC){      // only CTAs that run LSTM2 units
        float v = g_enc[tid];                   // NTHR == ENCN == 256
        float ws = wsum(v);
        if (lane == 0) s_ra[wid] = ws;
        __syncthreads();
        float tot = 0.f;
#pragma unroll
        for (int i = 0; i < WPC; i++) tot += s_ra[i];
        float mean = tot * (1.0f/ENCN);
        float d = v - mean;
        float ws2 = wsum(d*d);
        if (lane == 0) s_rb[wid] = ws2;
        __syncthreads();
        float tot2 = 0.f;
#pragma unroll
        for (int i = 0; i < WPC; i++) tot2 += s_rb[i];
        float rstd = rsqrtf(tot2 * (1.0f/ENCN) + 1e-7f);
        s_encn[tid] = d * rstd * gamma_[tid] + beta_[tid];
        __syncthreads();

        if (gw < HID){
            int j = gw;
            lstm_unit(j, lane, s_encn, ENCN, st2 /*h layer0*/,
                      wih20, whh20, bih20, bhh20, st2[2*HID + j],
                      &g_h1b[j], &out[WIN + 4*HID + j], &out[WIN + 6*HID + j]);
        }
    }
    gsync();

    // ---- Stage 7: LSTM2 layer1 ----
    if (gw < HID){
        int j = gw;
        lstm_unit(j, lane, g_h1b, HID, st2 + HID,
                  wih21, whh21, bih21, bhh21, st2[3*HID + j],
                  &g_h2b[j], &out[WIN + 5*HID + j], &out[WIN + 7*HID + j]);
    }
    gsync();

    // ---- Stage 8: dense2 mask, est_enc ----
    for (int r = gw; r < ENCN; r += TOTW){
        const float* wr = d2w + (size_t)r*HID;
        float acc = 0.f;
#pragma unroll
        for (int k = lane; k < HID; k += 32) acc = fmaf(wr[k], g_h2b[k], acc);
        acc = wsum(acc);
        if (lane == 0) g_est[r] = sigm(acc + d2b[r]) * g_enc[r];
    }
    gsync();

    // ---- Stage 9: decoder matvec (1024 x 256) ----
    for (int w = gw; w < WIN; w += TOTW){
        const float* wr = decw + (size_t)w*ENCN;
        float acc = 0.f;
#pragma unroll
        for (int e = lane; e < ENCN; e += 32) acc = fmaf(wr[e], g_est[e], acc);
        acc = wsum(acc);
        if (lane == 0) out[w] = acc;
    }
}

extern "C" void kernel_launch(void* const* d_in, const int* in_sizes, int n_in,
                              void* d_out, int out_size)
{
    (void)in_sizes; (void)n_in; (void)out_size;
    dtln_kernel<<<NBLK, NTHR>>>(
        (const float*)d_in[0],  (const float*)d_in[1],
        (const float*)d_in[2],  (const float*)d_in[3],
        (const float*)d_in[4],  (const float*)d_in[5],
        (const float*)d_in[6],  (const float*)d_in[7],
        (const float*)d_in[8],  (const float*)d_in[9],
        (const float*)d_in[10], (const float*)d_in[11],
        (const float*)d_in[12], (const float*)d_in[13],
        (const float*)d_in[14], (const float*)d_in[15],
        (const float*)d_in[16],
        (const float*)d_in[17], (const float*)d_in[18],
        (const float*)d_in[19], (const float*)d_in[20],
        (const float*)d_in[21], (const float*)d_in[22],
        (const float*)d_in[23], (const float*)d_in[24],
        (const float*)d_in[25], (const float*)d_in[26],
        (const float*)d_in[27],
        (float*)d_out);
}

// round 2
// speedup vs baseline: 1.3617x; 1.3617x over previous
#include <cuda_runtime.h>
#include <math.h>

#define NBLK 128
#define NTHR 256
#define WPC  8
#define TOTW (NBLK*WPC)
#define HID  128
#define BINS 513
#define WIN  1024
#define ENCN 256

// ---------------- device scratch ----------------
__device__ float g_h1[HID], g_h2[HID], g_h1b[HID], g_h2b[HID];
__device__ float g_specr[BINS], g_speci[BINS];
__device__ float g_y1[WIN];
__device__ float g_enc[ENCN];
__device__ float g_est[ENCN];
__device__ unsigned g_barcnt;
__device__ unsigned g_bargen;

__device__ __forceinline__ float wsum(float v){
#pragma unroll
    for (int o = 16; o > 0; o >>= 1) v += __shfl_xor_sync(0xffffffffu, v, o);
    return v;
}
__device__ __forceinline__ float sigm(float x){ return 1.0f/(1.0f+__expf(-x)); }

// Grid barrier: whole grid is wave-1 resident (128 CTAs on 148+ SMs, occ 1).
__device__ __forceinline__ void gsync(){
    __threadfence();
    __syncthreads();
    if (threadIdx.x == 0){
        unsigned gen = *((volatile unsigned*)&g_bargen);
        if (atomicAdd(&g_barcnt, 1u) == NBLK-1){
            g_barcnt = 0;
            __threadfence();
            atomicAdd(&g_bargen, 1u);
        } else {
            while (*((volatile unsigned*)&g_bargen) == gen) { }
        }
    }
    __syncthreads();
    __threadfence();
}

// Preload LSTM unit j's weights/biases/prev-state into registers.
template<int NX, int NXR>
__device__ __forceinline__ void lstm_preload(
    int j, int lane,
    const float* __restrict__ wih, const float* __restrict__ whh,
    const float* __restrict__ bih, const float* __restrict__ bhh,
    const float* __restrict__ hvec,
    float wi[4][17], float wh[4][4], float hr[4], float bsum[4])
{
#pragma unroll
    for (int g = 0; g < 4; g++){
        const float* w = wih + (size_t)(g*HID + j)*NX;
#pragma unroll
        for (int i = 0; i < NXR; i++){
            int k = lane + 32*i;
            wi[g][i] = ((NX & 31) == 0 || k < NX) ? w[k] : 0.f;
        }
        const float* whp = whh + (size_t)(g*HID + j)*HID;
#pragma unroll
        for (int i = 0; i < 4; i++) wh[g][i] = whp[lane + 32*i];
        bsum[g] = bih[g*HID + j] + bhh[g*HID + j];
    }
#pragma unroll
    for (int i = 0; i < 4; i++) hr[i] = hvec[lane + 32*i];
}

// Compute LSTM unit from preloaded registers + fresh input vector xr.
template<int NXR>
__device__ __forceinline__ void lstm_fire(
    int lane, const float wi[4][17], const float wh[4][4],
    const float* xr, const float hr[4], const float bsum[4],
    float cprev, float* hdst, float* hout, float* cout)
{
    float a[4];
#pragma unroll
    for (int g = 0; g < 4; g++){
        float acc = 0.f;
#pragma unroll
        for (int i = 0; i < NXR; i++) acc = fmaf(wi[g][i], xr[i], acc);
#pragma unroll
        for (int i = 0; i < 4; i++)   acc = fmaf(wh[g][i], hr[i], acc);
        a[g] = wsum(acc) + bsum[g];
    }
    if (lane == 0){
        float c2 = sigm(a[1])*cprev + sigm(a[0])*tanhf(a[2]);
        float h2 = sigm(a[3])*tanhf(c2);
        *hdst = h2; *hout = h2; *cout = c2;
    }
}

__global__ void __launch_bounds__(NTHR) dtln_kernel(
    const float* __restrict__ mag,   const float* __restrict__ phase,
    const float* __restrict__ st1,   const float* __restrict__ st2,
    const float* __restrict__ wih10, const float* __restrict__ whh10,
    const float* __restrict__ bih10, const float* __restrict__ bhh10,
    const float* __restrict__ wih11, const float* __restrict__ whh11,
    const float* __restrict__ bih11, const float* __restrict__ bhh11,
    const float* __restrict__ d1w,   const float* __restrict__ d1b,
    const float* __restrict__ encw,  const float* __restrict__ gamma_,
    const float* __restrict__ beta_,
    const float* __restrict__ wih20, const float* __restrict__ whh20,
    const float* __restrict__ bih20, const float* __restrict__ bhh20,
    const float* __restrict__ wih21, const float* __restrict__ whh21,
    const float* __restrict__ bih21, const float* __restrict__ bhh21,
    const float* __restrict__ d2w,   const float* __restrict__ d2b,
    const float* __restrict__ decw,
    float* __restrict__ out)
{
    const int tid  = threadIdx.x;
    const int lane = tid & 31;
    const int wid  = tid >> 5;
    const int cta  = blockIdx.x;
    const int gw   = cta * WPC + wid;      // 0..1023

    __shared__ float s_twc[WIN], s_tws[WIN];
    __shared__ float s_encn[ENCN];
    __shared__ float s_red[WPC];

    // Twiddle table per CTA (independent of inputs).
#pragma unroll
    for (int i = 0; i < WIN/NTHR; i++){
        int m = tid + NTHR*i;
        float s, c; sincospif((float)m * (1.0f/512.0f), &s, &c);
        s_twc[m] = c; s_tws[m] = s;
    }

    // =============== PRELOADS (all constant data -> registers) ===============
    float decr[8];
    {
        const float* wr = decw + (size_t)gw*ENCN;
#pragma unroll
        for (int i = 0; i < 8; i++) decr[i] = wr[lane + 32*i];
    }

    float wi[4][17], wh4[4][4], hr[4], bsum[4], cprev = 0.f;
    float d1r[4], d1bias = 0.f, magr = 0.f, cphr = 0.f, sphr = 0.f;
    float wrow[32];
    float d2r[4], d2bias = 0.f;
    float gam = 0.f, bet = 0.f;

    if (gw < 128){
        lstm_preload<BINS,17>(gw, lane, wih10, whh10, bih10, bhh10, st1, wi, wh4, hr, bsum);
        cprev = st1[2*HID + gw];
    } else if (gw < 256){
        int j = gw - 128;
        lstm_preload<HID,4>(j, lane, wih11, whh11, bih11, bhh11, st1 + HID, wi, wh4, hr, bsum);
        cprev = st1[3*HID + j];
    } else if (gw < 384){
        int j = gw - 256;
        lstm_preload<ENCN,8>(j, lane, wih20, whh20, bih20, bhh20, st2, wi, wh4, hr, bsum);
        cprev = st2[2*HID + j];
    } else if (gw < 512){
        int j = gw - 384;
        lstm_preload<HID,4>(j, lane, wih21, whh21, bih21, bhh21, st2 + HID, wi, wh4, hr, bsum);
        cprev = st2[3*HID + j];
    } else if (gw < 768){
        const float* wr = encw + (size_t)(gw - 512)*WIN;
#pragma unroll
        for (int i = 0; i < 32; i++) wrow[i] = wr[lane + 32*i];
    }
    if (gw >= 256 && gw < 769){
        int r = gw - 256;
        const float* wr = d1w + (size_t)r*HID;
#pragma unroll
        for (int i = 0; i < 4; i++) d1r[i] = wr[lane + 32*i];
        d1bias = d1b[r];
        magr   = mag[r];
        sincosf(phase[r], &sphr, &cphr);
    }
    if (gw >= 768){
        int r = gw - 768;
        const float* wr = d2w + (size_t)r*HID;
#pragma unroll
        for (int i = 0; i < 4; i++) d2r[i] = wr[lane + 32*i];
        d2bias = d2b[r];
    }
    if (cta >= 32 && cta < 48){ gam = gamma_[tid]; bet = beta_[tid]; }

    // =============== Stage 1: LSTM1 layer0 (no barrier needed before) ========
    if (gw < 128){
        float xr[17];
#pragma unroll
        for (int i = 0; i < 17; i++){ int k = lane + 32*i; xr[i] = (k < BINS) ? mag[k] : 0.f; }
        lstm_fire<17>(lane, wi, wh4, xr, hr, bsum, cprev,
                      &g_h1[gw], &out[WIN + gw], &out[WIN + 2*HID + gw]);
    }
    gsync();

    // =============== Stage 2: LSTM1 layer1 ===================================
    if (gw >= 128 && gw < 256){
        int j = gw - 128;
        float xr[4];
#pragma unroll
        for (int i = 0; i < 4; i++) xr[i] = g_h1[lane + 32*i];
        lstm_fire<4>(lane, wi, wh4, xr, hr, bsum, cprev,
                     &g_h2[j], &out[WIN + HID + j], &out[WIN + 3*HID + j]);
    }
    gsync();

    // =============== Stage 3: dense1 mask -> complex spectrum ================
    if (gw >= 256 && gw < 769){
        int r = gw - 256;
        float xr[4];
#pragma unroll
        for (int i = 0; i < 4; i++) xr[i] = g_h2[lane + 32*i];
        float acc = 0.f;
#pragma unroll
        for (int i = 0; i < 4; i++) acc = fmaf(d1r[i], xr[i], acc);
        acc = wsum(acc);
        if (lane == 0){
            float em = sigm(acc + d1bias) * magr;
            g_specr[r] = em * cphr;
            g_speci[r] = em * sphr;
        }
    }
    gsync();

    // =============== Stage 4: iRFFT (real DFT, twiddle table) ================
    {
        int n = gw;
        float acc = 0.f;
#pragma unroll
        for (int t = 0; t < 16; t++){
            int k = 1 + lane + 32*t;
            if (k < 512){
                int idx = (k * n) & (WIN - 1);
                acc += g_specr[k]*s_twc[idx] - g_speci[k]*s_tws[idx];
            }
        }
        acc = wsum(acc);
        if (lane == 0){
            float nyq = (n & 1) ? -g_specr[512] : g_specr[512];
            g_y1[n] = (g_specr[0] + 2.0f*acc + nyq) * (1.0f/1024.0f);
        }
    }
    gsync();

    // =============== Stage 5: encoder (256 x 1024) ===========================
    if (gw >= 512 && gw < 768){
        float acc = 0.f;
#pragma unroll
        for (int i = 0; i < 32; i++) acc = fmaf(wrow[i], g_y1[lane + 32*i], acc);
        acc = wsum(acc);
        if (lane == 0) g_enc[gw - 512] = acc;
    }
    gsync();

    // =============== Stage 6: instance-norm + LSTM2 layer0 ===================
    if (cta >= 32 && cta < 48){
        float v  = g_enc[tid];                    // NTHR == ENCN
        float t1 = wsum(v);
        if (lane == 0) s_red[wid] = t1;
        __syncthreads();
        float tot = 0.f;
#pragma unroll
        for (int i = 0; i < WPC; i++) tot += s_red[i];
        float mean = tot * (1.0f/ENCN);
        float d = v - mean;
        float t2 = wsum(d*d);
        __syncthreads();
        if (lane == 0) s_red[wid] = t2;
        __syncthreads();
        float tot2 = 0.f;
#pragma unroll
        for (int i = 0; i < WPC; i++) tot2 += s_red[i];
        float rstd = rsqrtf(tot2 * (1.0f/ENCN) + 1e-7f);
        s_encn[tid] = d * rstd * gam + bet;
        __syncthreads();

        int j = gw - 256;
        float xr[8];
#pragma unroll
        for (int i = 0; i < 8; i++) xr[i] = s_encn[lane + 32*i];
        lstm_fire<8>(lane, wi, wh4, xr, hr, bsum, cprev,
                     &g_h1b[j], &out[WIN + 4*HID + j], &out[WIN + 6*HID + j]);
    }
    gsync();

    // =============== Stage 7: LSTM2 layer1 ===================================
    if (gw >= 384 && gw < 512){
        int j = gw - 384;
        float xr[4];
#pragma unroll
        for (int i = 0; i < 4; i++) xr[i] = g_h1b[lane + 32*i];
        lstm_fire<4>(lane, wi, wh4, xr, hr, bsum, cprev,
                     &g_h2b[j], &out[WIN + 5*HID + j], &out[WIN + 7*HID + j]);
    }
    gsync();

    // =============== Stage 8: dense2 mask * enc ==============================
    if (gw >= 768){
        int r = gw - 768;
        float encv = g_enc[r];                    // ready since stage 5
        float xr[4];
#pragma unroll
        for (int i = 0; i < 4; i++) xr[i] = g_h2b[lane + 32*i];
        float acc = 0.f;
#pragma unroll
        for (int i = 0; i < 4; i++) acc = fmaf(d2r[i], xr[i], acc);
        acc = wsum(acc);
        if (lane == 0) g_est[r] = sigm(acc + d2bias) * encv;
    }
    gsync();

    // =============== Stage 9: decoder (1024 x 256) ===========================
    {
        float xr[8];
#pragma unroll
        for (int i = 0; i < 8; i++) xr[i] = g_est[lane + 32*i];
        float acc = 0.f;
#pragma unroll
        for (int i = 0; i < 8; i++) acc = fmaf(decr[i], xr[i], acc);
        acc = wsum(acc);
        if (lane == 0) out[gw] = acc;
    }
}

extern "C" void kernel_launch(void* const* d_in, const int* in_sizes, int n_in,
                              void* d_out, int out_size)
{
    (void)in_sizes; (void)n_in; (void)out_size;
    dtln_kernel<<<NBLK, NTHR>>>(
        (const float*)d_in[0],  (const float*)d_in[1],
        (const float*)d_in[2],  (const float*)d_in[3],
        (const float*)d_in[4],  (const float*)d_in[5],
        (const float*)d_in[6],  (const float*)d_in[7],
        (const float*)d_in[8],  (const float*)d_in[9],
        (const float*)d_in[10], (const float*)d_in[11],
        (const float*)d_in[12], (const float*)d_in[13],
        (const float*)d_in[14], (const float*)d_in[15],
        (const float*)d_in[16],
        (const float*)d_in[17], (const float*)d_in[18],
        (const float*)d_in[19], (const float*)d_in[20],
        (const float*)d_in[21], (const float*)d_in[22],
        (const float*)d_in[23], (const float*)d_in[24],
        (const float*)d_in[25], (const float*)d_in[26],
        (const float*)d_in[27],
        (float*)d_out);
}